// round 12
// baseline (speedup 1.0000x reference)
#include <cuda_runtime.h>
#include <cuda_bf16.h>
#include <stdint.h>
#include <math.h>

#define D_MODEL 1024
#define N_HEAD 16
#define HEAD_DIM 64
#define BATCH 2
#define SEQ 2048
#define M_ROWS (BATCH * SEQ)   // 4096
#define KP 3072                // split K' = 3*1024 for projections
#define AKP 192                // split K' = 3*64 for attention scores
#define AVP 128                // V split width (vh|vl)

// ---------------- scratch ----------------
__device__ float g_q[M_ROWS * D_MODEL];
__device__ float g_k[M_ROWS * D_MODEL];
__device__ float g_v[M_ROWS * D_MODEL];

__device__ __nv_bfloat16 g_x2[M_ROWS * KP];      // [Ah | Ah | Al]
__device__ __nv_bfloat16 g_ctx2[M_ROWS * KP];    // written by attention epilogue
__device__ __nv_bfloat16 g_wq2[D_MODEL * KP];    // [Wh^T | Wl^T | Wh^T]
__device__ __nv_bfloat16 g_wk2[D_MODEL * KP];
__device__ __nv_bfloat16 g_wv2[D_MODEL * KP];
__device__ __nv_bfloat16 g_wo2[D_MODEL * KP];

__device__ __nv_bfloat16 g_Q2[32 * SEQ * AKP];           // [bh][s][qh|qh|ql] (scale*log2e folded)
__device__ __nv_bfloat16 g_K2[32 * SEQ * AKP];           // [bh][s][kh|kl|kh]
__device__ __nv_bfloat16 g_Vt2[32 * HEAD_DIM * 2 * SEQ]; // [bh][dh][t: vh(64)|vl(64)]

// ============================================================================
// helpers
// ============================================================================
__device__ __forceinline__ void split_bf16(float x, __nv_bfloat16& h, __nv_bfloat16& l)
{
    h = __float2bfloat16(x);
    l = __float2bfloat16(x - __bfloat162float(h));
}

__device__ __forceinline__ float ex2f(float x)
{
    float y;
    asm("ex2.approx.ftz.f32 %0, %1;" : "=f"(y) : "f"(x));
    return y;
}

__device__ __forceinline__ void mma16816(float c[4],
    uint32_t a0, uint32_t a1, uint32_t a2, uint32_t a3, uint32_t b0, uint32_t b1)
{
    asm volatile(
        "mma.sync.aligned.m16n8k16.row.col.f32.bf16.bf16.f32 "
        "{%0,%1,%2,%3}, {%4,%5,%6,%7}, {%8,%9}, {%0,%1,%2,%3};\n"
        : "+f"(c[0]), "+f"(c[1]), "+f"(c[2]), "+f"(c[3])
        : "r"(a0), "r"(a1), "r"(a2), "r"(a3), "r"(b0), "r"(b1));
}

__device__ __forceinline__ void ldsm4(uint32_t& r0, uint32_t& r1, uint32_t& r2, uint32_t& r3,
                                      const void* p)
{
    uint32_t a = (uint32_t)__cvta_generic_to_shared(p);
    asm volatile("ldmatrix.sync.aligned.m8n8.x4.shared.b16 {%0,%1,%2,%3}, [%4];\n"
                 : "=r"(r0), "=r"(r1), "=r"(r2), "=r"(r3) : "r"(a));
}

__device__ __forceinline__ void cpa16(void* sdst, const void* gsrc)
{
    uint32_t sa = (uint32_t)__cvta_generic_to_shared(sdst);
    asm volatile("cp.async.cg.shared.global [%0], [%1], 16;\n" :: "r"(sa), "l"(gsrc));
}
__device__ __forceinline__ void cpa_commit() { asm volatile("cp.async.commit_group;\n"); }
template <int N>
__device__ __forceinline__ void cpa_wait() { asm volatile("cp.async.wait_group %0;\n" :: "n"(N)); }

// ============================================================================
// Split input rows: X[M][1024] fp32 -> X2[M][3072] bf16 = [h | h | l]
// ============================================================================
__global__ void split_rows_kernel(const float* __restrict__ X,
                                  __nv_bfloat16* __restrict__ X2, int M)
{
    int idx = blockIdx.x * blockDim.x + threadIdx.x;
    if (idx >= M * 512) return;
    int r = idx >> 9;
    int c = (idx & 511) * 2;
    float2 v = *(const float2*)&X[(size_t)r * D_MODEL + c];
    __nv_bfloat16 h0, l0, h1, l1;
    split_bf16(v.x, h0, l0);
    split_bf16(v.y, h1, l1);
    __nv_bfloat162 hh; hh.x = h0; hh.y = h1;
    __nv_bfloat162 ll; ll.x = l0; ll.y = l1;
    size_t base = (size_t)r * KP + c;
    *(__nv_bfloat162*)&X2[base]             = hh;
    *(__nv_bfloat162*)&X2[base + D_MODEL]   = hh;
    *(__nv_bfloat162*)&X2[base + 2*D_MODEL] = ll;
}

// Split + transpose weights: W[K][N] fp32 -> B2t[N][3072] = [h | l | h]
__global__ void split_wT_kernel(const float* __restrict__ W,
                                __nv_bfloat16* __restrict__ B2t)
{
    __shared__ float t[32][33];
    const int k0 = blockIdx.y * 32, n0 = blockIdx.x * 32;
    const int tx = threadIdx.x, ty = threadIdx.y;
#pragma unroll
    for (int i = 0; i < 4; i++)
        t[ty + i * 8][tx] = W[(size_t)(k0 + ty + i * 8) * D_MODEL + n0 + tx];
    __syncthreads();
#pragma unroll
    for (int i = 0; i < 4; i++) {
        int n = n0 + ty + i * 8;
        int k = k0 + tx;
        float v = t[tx][ty + i * 8];
        __nv_bfloat16 h, l;
        split_bf16(v, h, l);
        size_t base = (size_t)n * KP;
        B2t[base + k]              = h;
        B2t[base + D_MODEL + k]    = l;
        B2t[base + 2*D_MODEL + k]  = h;
    }
}

// ============================================================================
// Q/K attention split. Q gets scale*log2(e) folded (exp2 domain).
// ============================================================================
__global__ void qk2_split_kernel(const float* __restrict__ Qf,
                                 const float* __restrict__ Kf,
                                 __nv_bfloat16* __restrict__ Q2,
                                 __nv_bfloat16* __restrict__ K2)
{
    const float QSCALE = 0.125f * 1.44269504088896f;
    int idx = blockIdx.x * blockDim.x + threadIdx.x;
    if (idx >= M_ROWS * 512) return;
    int r  = idx >> 9;
    int c2 = (idx & 511) * 2;
    int h  = c2 >> 6;
    int d  = c2 & 63;
    int b  = r / SEQ, s = r % SEQ;
    int bh = b * N_HEAD + h;
    size_t base = ((size_t)bh * SEQ + s) * AKP;

    float2 qv = *(const float2*)&Qf[(size_t)r * D_MODEL + c2];
    qv.x *= QSCALE; qv.y *= QSCALE;
    __nv_bfloat16 qh0, ql0, qh1, ql1;
    split_bf16(qv.x, qh0, ql0);
    split_bf16(qv.y, qh1, ql1);
    __nv_bfloat162 qh; qh.x = qh0; qh.y = qh1;
    __nv_bfloat162 ql; ql.x = ql0; ql.y = ql1;
    *(__nv_bfloat162*)&Q2[base + d]       = qh;
    *(__nv_bfloat162*)&Q2[base + 64 + d]  = qh;
    *(__nv_bfloat162*)&Q2[base + 128 + d] = ql;

    float2 kv = *(const float2*)&Kf[(size_t)r * D_MODEL + c2];
    __nv_bfloat16 kh0, kl0, kh1, kl1;
    split_bf16(kv.x, kh0, kl0);
    split_bf16(kv.y, kh1, kl1);
    __nv_bfloat162 kh; kh.x = kh0; kh.y = kh1;
    __nv_bfloat162 kl; kl.x = kl0; kl.y = kl1;
    *(__nv_bfloat162*)&K2[base + d]       = kh;
    *(__nv_bfloat162*)&K2[base + 64 + d]  = kl;
    *(__nv_bfloat162*)&K2[base + 128 + d] = kh;
}

// ============================================================================
// V transpose+split: fp32 -> Vt2[bh][dh][t*128 + {vh(64)|vl(64)}]
// ============================================================================
__global__ void vt2_split_kernel(const float* __restrict__ Vf,
                                 __nv_bfloat16* __restrict__ Vt2)
{
    __shared__ float tile[64][65];
    const int t  = blockIdx.x;
    const int bh = blockIdx.y;
    const int b  = bh >> 4, h = bh & 15;
    const int tid = threadIdx.x;

#pragma unroll
    for (int i = 0; i < 16; i++) {
        int e = i * 256 + tid;
        int s = e >> 6, d = e & 63;
        tile[s][d] = Vf[((size_t)(b * SEQ + t * 64 + s)) * D_MODEL + h * 64 + d];
    }
    __syncthreads();
#pragma unroll
    for (int i = 0; i < 16; i++) {
        int e  = i * 256 + tid;
        int dh = e >> 6, kv = e & 63;
        float v = tile[kv][dh];
        __nv_bfloat16 vh, vl;
        split_bf16(v, vh, vl);
        size_t base = ((size_t)bh * 64 + dh) * (2 * SEQ) + (size_t)t * AVP;
        Vt2[base + kv]       = vh;
        Vt2[base + 64 + kv]  = vl;
    }
}

// ============================================================================
// bf16 tensor-core GEMM (plain fp32 epilogue). blockIdx.z selects (Bt, C).
// ============================================================================
#define TBK 32
#define TLD 40

__global__ __launch_bounds__(256)
void gemm_bf16_kernel(const __nv_bfloat16* __restrict__ A,
                      const __nv_bfloat16* __restrict__ Bt0,
                      const __nv_bfloat16* __restrict__ Bt1,
                      const __nv_bfloat16* __restrict__ Bt2,
                      float* __restrict__ C0,
                      float* __restrict__ C1,
                      float* __restrict__ C2,
                      int N)
{
    const __nv_bfloat16* Bt = (blockIdx.z == 0) ? Bt0 : (blockIdx.z == 1) ? Bt1 : Bt2;
    float* C = (blockIdx.z == 0) ? C0 : (blockIdx.z == 1) ? C1 : C2;

    __shared__ __nv_bfloat16 As[128 * TLD];
    __shared__ __nv_bfloat16 Bs[128 * TLD];

    const int tid  = threadIdx.x;
    const int wid  = tid >> 5;
    const int lane = tid & 31;
    const int g    = lane >> 2;
    const int q4   = lane & 3;
    const int warp_m = wid >> 2;
    const int warp_n = wid & 3;
    const int rowBase = blockIdx.y * 128;
    const int colBase = blockIdx.x * 128;

    float acc[4][4][4];
#pragma unroll
    for (int im = 0; im < 4; im++)
#pragma unroll
        for (int in = 0; in < 4; in++)
#pragma unroll
            for (int e = 0; e < 4; e++) acc[im][in][e] = 0.f;

    uint4 pa[2], pb[2];
    const int lr0 = tid >> 2;
    const int lc  = (tid & 3) * 8;

    auto loadTile = [&](int k0) {
        pa[0] = *(const uint4*)&A [(size_t)(rowBase + lr0)      * KP + k0 + lc];
        pa[1] = *(const uint4*)&A [(size_t)(rowBase + lr0 + 64) * KP + k0 + lc];
        pb[0] = *(const uint4*)&Bt[(size_t)(colBase + lr0)      * KP + k0 + lc];
        pb[1] = *(const uint4*)&Bt[(size_t)(colBase + lr0 + 64) * KP + k0 + lc];
    };
    auto storeTile = [&]() {
        *(uint4*)&As[(lr0)      * TLD + lc] = pa[0];
        *(uint4*)&As[(lr0 + 64) * TLD + lc] = pa[1];
        *(uint4*)&Bs[(lr0)      * TLD + lc] = pb[0];
        *(uint4*)&Bs[(lr0 + 64) * TLD + lc] = pb[1];
    };

    loadTile(0);
    storeTile();
    __syncthreads();

    for (int k0 = 0; k0 < KP; k0 += TBK) {
        bool more = (k0 + TBK) < KP;
        if (more) loadTile(k0 + TBK);

#pragma unroll
        for (int ks = 0; ks < 2; ks++) {
            const int kk = ks * 16 + q4 * 2;
            uint32_t bfr[4][2];
#pragma unroll
            for (int in = 0; in < 4; in++) {
                int n = warp_n * 32 + in * 8 + g;
                bfr[in][0] = *(const uint32_t*)&Bs[n * TLD + kk];
                bfr[in][1] = *(const uint32_t*)&Bs[n * TLD + kk + 8];
            }
#pragma unroll
            for (int im = 0; im < 4; im++) {
                int r = warp_m * 64 + im * 16 + g;
                uint32_t a0 = *(const uint32_t*)&As[(r)     * TLD + kk];
                uint32_t a1 = *(const uint32_t*)&As[(r + 8) * TLD + kk];
                uint32_t a2 = *(const uint32_t*)&As[(r)     * TLD + kk + 8];
                uint32_t a3 = *(const uint32_t*)&As[(r + 8) * TLD + kk + 8];
#pragma unroll
                for (int in = 0; in < 4; in++)
                    mma16816(acc[im][in], a0, a1, a2, a3, bfr[in][0], bfr[in][1]);
            }
        }
        __syncthreads();
        if (more) {
            storeTile();
            __syncthreads();
        }
    }

#pragma unroll
    for (int im = 0; im < 4; im++) {
        int r0 = rowBase + warp_m * 64 + im * 16 + g;
#pragma unroll
        for (int in = 0; in < 4; in++) {
            int col = colBase + warp_n * 32 + in * 8 + q4 * 2;
            float2 v0 = make_float2(acc[im][in][0], acc[im][in][1]);
            float2 v1 = make_float2(acc[im][in][2], acc[im][in][3]);
            *(float2*)&C[(size_t)(r0)     * N + col] = v0;
            *(float2*)&C[(size_t)(r0 + 8) * N + col] = v1;
        }
    }
}

// ============================================================================
// Tensor-core causal flash attention — software-pipelined:
// iteration t runs PV(t) INTERLEAVED with QK(t+1) (two independent mma chains),
// then softmax(t+1) overlapping tile t+2's cp.async. 3 smem buffers, 1 CTA/SM.
// CTA = (b,h) x 128 q rows; 8 warps x 16 q rows; BKV = 64.
// ============================================================================
#define KLD 200                         // K tile leading dim (elems)
#define VLD 136                         // V tile leading dim (elems)
#define KT_E (64 * KLD)                 // 12800 elems
#define VT_E (64 * VLD)                 // 8704 elems
#define BUF_E (KT_E + VT_E)             // 21504 elems
#define NSTG 3
#define ATT_SMEM (NSTG * BUF_E * 2)     // 129024 bytes

extern __shared__ __nv_bfloat16 attn_sm[];

__global__ __launch_bounds__(256)
void attn_tc_kernel(const __nv_bfloat16* __restrict__ Q2,
                    const __nv_bfloat16* __restrict__ K2,
                    const __nv_bfloat16* __restrict__ Vt2,
                    __nv_bfloat16* __restrict__ ctx2)
{
    const int tid  = threadIdx.x;
    const int w    = tid >> 5;
    const int lane = tid & 31;
    const int g    = lane >> 2;
    const int q4   = lane & 3;
    const int bh   = blockIdx.y;
    const int b    = bh >> 4, h = bh & 15;
    const int q0   = (gridDim.x - 1 - blockIdx.x) * 128;   // heavy CTAs first
    const int nt   = q0 / 64 + 2;
    const int qw   = q0 + w * 16;

    // per-lane LDSM base offsets
    const int rowN  = lane & 7;
    const int ksel  = (lane >> 3) & 1;
    const int jsel  = lane >> 4;
    const int kOffE = (jsel * 8 + rowN) * KLD + ksel * 8;
    const int vOffE = (jsel * 8 + rowN) * VLD + ksel * 8;

    // ---- Q fragments in registers (12 ksteps) ----
    uint32_t qa[12][4];
    {
        const __nv_bfloat16* Qbase = Q2 + ((size_t)bh * SEQ + qw) * AKP;
#pragma unroll
        for (int ks = 0; ks < 12; ks++) {
            int kk = ks * 16 + 2 * q4;
            qa[ks][0] = *(const uint32_t*)&Qbase[(g)     * AKP + kk];
            qa[ks][1] = *(const uint32_t*)&Qbase[(g + 8) * AKP + kk];
            qa[ks][2] = *(const uint32_t*)&Qbase[(g)     * AKP + kk + 8];
            qa[ks][3] = *(const uint32_t*)&Qbase[(g + 8) * AKP + kk + 8];
        }
    }

    const __nv_bfloat16* Kg = K2  + (size_t)bh * SEQ * AKP;
    const __nv_bfloat16* Vg = Vt2 + (size_t)bh * HEAD_DIM * (2 * SEQ);

    auto issueTile = [&](int t) {
        const __nv_bfloat16* ksrc = Kg + (size_t)t * 64 * AKP;
        const __nv_bfloat16* vsrc = Vg + (size_t)t * AVP;
        __nv_bfloat16* kd = attn_sm + (t % NSTG) * BUF_E;
        __nv_bfloat16* vd = kd + KT_E;
#pragma unroll
        for (int i = 0; i < 6; i++) {           // K: 64 rows x 24 chunks
            int c   = i * 256 + tid;
            int row = c / 24;
            int col = (c % 24) * 8;
            cpa16(&kd[row * KLD + col], &ksrc[row * AKP + col]);
        }
#pragma unroll
        for (int i = 0; i < 4; i++) {           // V: 64 rows x 16 chunks
            int c   = i * 256 + tid;
            int row = c >> 4;
            int col = (c & 15) * 8;
            cpa16(&vd[row * VLD + col], &vsrc[(size_t)row * (2 * SEQ) + col]);
        }
        cpa_commit();
    };

    float O[8][4];
#pragma unroll
    for (int j = 0; j < 8; j++)
#pragma unroll
        for (int e = 0; e < 4; e++) O[j][e] = 0.f;
    float m0 = -INFINITY, m1 = -INFINITY, l0 = 0.f, l1 = 0.f;

    float S_[8][4];
    uint32_t ph[8][2], pl[8][2];

    // softmax for tile u: masks S_, updates m/l, rescales O, fills ph/pl
    auto softmaxTile = [&](int u) {
        const int k0 = u * 64;
        if (k0 + 63 > qw) {
            const int r0 = qw + g, r1 = r0 + 8;
#pragma unroll
            for (int j = 0; j < 8; j++) {
                int c0 = k0 + j * 8 + 2 * q4;
                if (c0     > r0) S_[j][0] = -INFINITY;
                if (c0 + 1 > r0) S_[j][1] = -INFINITY;
                if (c0     > r1) S_[j][2] = -INFINITY;
                if (c0 + 1 > r1) S_[j][3] = -INFINITY;
            }
        }

        float rmax0 = -INFINITY, rmax1 = -INFINITY;
#pragma unroll
        for (int j = 0; j < 8; j++) {
            rmax0 = fmaxf(rmax0, fmaxf(S_[j][0], S_[j][1]));
            rmax1 = fmaxf(rmax1, fmaxf(S_[j][2], S_[j][3]));
        }
        rmax0 = fmaxf(rmax0, __shfl_xor_sync(0xffffffffu, rmax0, 1));
        rmax0 = fmaxf(rmax0, __shfl_xor_sync(0xffffffffu, rmax0, 2));
        rmax1 = fmaxf(rmax1, __shfl_xor_sync(0xffffffffu, rmax1, 1));
        rmax1 = fmaxf(rmax1, __shfl_xor_sync(0xffffffffu, rmax1, 2));

        float nm0 = fmaxf(m0, rmax0), nm1 = fmaxf(m1, rmax1);
        float corr0 = ex2f(m0 - nm0), corr1 = ex2f(m1 - nm1);
        m0 = nm0; m1 = nm1;

        float sum0 = 0.f, sum1 = 0.f;
#pragma unroll
        for (int j = 0; j < 8; j++) {
            float p00 = ex2f(S_[j][0] - nm0);
            float p01 = ex2f(S_[j][1] - nm0);
            float p10 = ex2f(S_[j][2] - nm1);
            float p11 = ex2f(S_[j][3] - nm1);
            sum0 += p00 + p01;
            sum1 += p10 + p11;
            __nv_bfloat16 h00, l00, h01, l01, h10, l10, h11, l11;
            split_bf16(p00, h00, l00); split_bf16(p01, h01, l01);
            split_bf16(p10, h10, l10); split_bf16(p11, h11, l11);
            __nv_bfloat162 t0; t0.x = h00; t0.y = h01;
            __nv_bfloat162 t1; t1.x = h10; t1.y = h11;
            __nv_bfloat162 t2; t2.x = l00; t2.y = l01;
            __nv_bfloat162 t3; t3.x = l10; t3.y = l11;
            ph[j][0] = *(uint32_t*)&t0; ph[j][1] = *(uint32_t*)&t1;
            pl[j][0] = *(uint32_t*)&t2; pl[j][1] = *(uint32_t*)&t3;
        }
        sum0 += __shfl_xor_sync(0xffffffffu, sum0, 1);
        sum0 += __shfl_xor_sync(0xffffffffu, sum0, 2);
        sum1 += __shfl_xor_sync(0xffffffffu, sum1, 1);
        sum1 += __shfl_xor_sync(0xffffffffu, sum1, 2);
        l0 = l0 * corr0 + sum0;
        l1 = l1 * corr1 + sum1;

#pragma unroll
        for (int j = 0; j < 8; j++) {
            O[j][0] *= corr0; O[j][1] *= corr0;
            O[j][2] *= corr1; O[j][3] *= corr1;
        }
    };

    // ---- prologue: load tiles 0,1; QK(0); softmax(0) ----
    issueTile(0);
    if (1 < nt) issueTile(1);
    cpa_wait<1>();
    __syncthreads();

    {
        const __nv_bfloat16* Ks = attn_sm;   // buf 0
#pragma unroll
        for (int j = 0; j < 8; j++)
#pragma unroll
            for (int e = 0; e < 4; e++) S_[j][e] = 0.f;
#pragma unroll
        for (int ks = 0; ks < 12; ks++) {
            uint32_t a0 = qa[ks][0], a1 = qa[ks][1], a2 = qa[ks][2], a3 = qa[ks][3];
#pragma unroll
            for (int jj = 0; jj < 4; jj++) {
                uint32_t b0, b1, b2, b3;
                ldsm4(b0, b1, b2, b3, Ks + kOffE + jj * 16 * KLD + ks * 16);
                mma16816(S_[2 * jj],     a0, a1, a2, a3, b0, b1);
                mma16816(S_[2 * jj + 1], a0, a1, a2, a3, b2, b3);
            }
        }
        softmaxTile(0);
    }

    // ---- main loop: iteration t = PV(t) interleaved with QK(t+1) ----
    for (int t = 0; t < nt; t++) {
        cpa_wait<0>();     // tiles <= t+1 fully loaded
        __syncthreads();   // and all warps done reading buffer (t+2)%3's old tile

        if (t + 2 < nt) issueTile(t + 2);   // buf (t+2)%3 distinct from t%3 and (t+1)%3

        const __nv_bfloat16* Vs  = attn_sm + (t % NSTG) * BUF_E + KT_E;       // V(t)
        const __nv_bfloat16* Ksn = attn_sm + ((t + 1) % NSTG) * BUF_E;        // K(t+1)

        const bool doPV = (t * 64 <= qw + 15);
        const bool doQK = (t + 1 < nt) && ((t + 1) * 64 <= qw + 15);

        if (doQK) {
#pragma unroll
            for (int j = 0; j < 8; j++)
#pragma unroll
                for (int e = 0; e < 4; e++) S_[j][e] = 0.f;
        }

        // interleaved 12-step region: QK kstep s + a slice of PV(t)
#pragma unroll
        for (int s = 0; s < 12; s++) {
            if (doQK) {
                uint32_t a0 = qa[s][0], a1 = qa[s][1], a2 = qa[s][2], a3 = qa[s][3];
#pragma unroll
                for (int jj = 0; jj < 4; jj++) {
                    uint32_t b0, b1, b2, b3;
                    ldsm4(b0, b1, b2, b3, Ksn + kOffE + jj * 16 * KLD + s * 16);
                    mma16816(S_[2 * jj],     a0, a1, a2, a3, b0, b1);
                    mma16816(S_[2 * jj + 1], a0, a1, a2, a3, b2, b3);
                }
            }
            if (doPV) {
                if (s < 4) {
                    // vh phase ksp = s: ph + pl (V-fragment reuse)
                    const int ksp = s;
                    uint32_t h0 = ph[2 * ksp][0],      h1 = ph[2 * ksp][1];
                    uint32_t h2 = ph[2 * ksp + 1][0],  h3 = ph[2 * ksp + 1][1];
                    uint32_t lo0 = pl[2 * ksp][0],     lo1 = pl[2 * ksp][1];
                    uint32_t lo2 = pl[2 * ksp + 1][0], lo3 = pl[2 * ksp + 1][1];
#pragma unroll
                    for (int jj = 0; jj < 4; jj++) {
                        uint32_t b0, b1, b2, b3;
                        ldsm4(b0, b1, b2, b3, Vs + vOffE + jj * 16 * VLD + ksp * 16);
                        mma16816(O[2 * jj],     h0, h1, h2, h3, b0, b1);
                        mma16816(O[2 * jj + 1], h0, h1, h2, h3, b2, b3);
                        mma16816(O[2 * jj],     lo0, lo1, lo2, lo3, b0, b1);
                        mma16816(O[2 * jj + 1], lo0, lo1, lo2, lo3, b2, b3);
                    }
                } else if (s < 8) {
                    // vl phase ksp = s-4: ph only
                    const int ksp = s - 4;
                    uint32_t h0 = ph[2 * ksp][0],     h1 = ph[2 * ksp][1];
                    uint32_t h2 = ph[2 * ksp + 1][0], h3 = ph[2 * ksp + 1][1];
#pragma unroll
                    for (int jj = 0; jj < 4; jj++) {
                        uint32_t b0, b1, b2, b3;
                        ldsm4(b0, b1, b2, b3, Vs + vOffE + jj * 16 * VLD + 64 + ksp * 16);
                        mma16816(O[2 * jj],     h0, h1, h2, h3, b0, b1);
                        mma16816(O[2 * jj + 1], h0, h1, h2, h3, b2, b3);
                    }
                }
            }
        }

        // softmax(t+1): overwrites ph/pl (PV(t) already consumed them)
        if (doQK) softmaxTile(t + 1);
    }

    // ---- epilogue: write [h|h|l] bf16 split of ctx directly ----
    const float inv0 = 1.f / l0, inv1 = 1.f / l1;
    const int r0 = b * SEQ + qw + g;
    const int colBase = h * HEAD_DIM + 2 * q4;
#pragma unroll
    for (int jn = 0; jn < 8; jn++) {
        int col = colBase + jn * 8;
        float v00 = O[jn][0] * inv0, v01 = O[jn][1] * inv0;
        float v10 = O[jn][2] * inv1, v11 = O[jn][3] * inv1;
        __nv_bfloat16 h00, l00, h01, l01, h10, l10, h11, l11;
        split_bf16(v00, h00, l00); split_bf16(v01, h01, l01);
        split_bf16(v10, h10, l10); split_bf16(v11, h11, l11);
        __nv_bfloat162 hh0; hh0.x = h00; hh0.y = h01;
        __nv_bfloat162 ll0; ll0.x = l00; ll0.y = l01;
        __nv_bfloat162 hh1; hh1.x = h10; hh1.y = h11;
        __nv_bfloat162 ll1; ll1.x = l10; ll1.y = l11;
        size_t base0 = (size_t)r0 * KP + col;
        size_t base1 = base0 + (size_t)8 * KP;
        *(uint32_t*)&ctx2[base0]             = *(uint32_t*)&hh0;
        *(uint32_t*)&ctx2[base0 + D_MODEL]   = *(uint32_t*)&hh0;
        *(uint32_t*)&ctx2[base0 + 2*D_MODEL] = *(uint32_t*)&ll0;
        *(uint32_t*)&ctx2[base1]             = *(uint32_t*)&hh1;
        *(uint32_t*)&ctx2[base1 + D_MODEL]   = *(uint32_t*)&hh1;
        *(uint32_t*)&ctx2[base1 + 2*D_MODEL] = *(uint32_t*)&ll1;
    }
}

// ============================================================================
// Launch
// ============================================================================
extern "C" void kernel_launch(void* const* d_in, const int* in_sizes, int n_in,
                              void* d_out, int out_size)
{
    const float* x  = (const float*)d_in[0];
    const float* Wq = (const float*)d_in[1];
    const float* Wk = (const float*)d_in[2];
    const float* Wv = (const float*)d_in[3];
    const float* Wo = (const float*)d_in[4];
    float* out = (float*)d_out;

    float *q, *k, *v;
    __nv_bfloat16 *x2, *ctx2, *wq2, *wk2, *wv2, *wo2, *Q2, *K2, *Vt2;
    cudaGetSymbolAddress((void**)&q,    g_q);
    cudaGetSymbolAddress((void**)&k,    g_k);
    cudaGetSymbolAddress((void**)&v,    g_v);
    cudaGetSymbolAddress((void**)&x2,   g_x2);
    cudaGetSymbolAddress((void**)&ctx2, g_ctx2);
    cudaGetSymbolAddress((void**)&wq2,  g_wq2);
    cudaGetSymbolAddress((void**)&wk2,  g_wk2);
    cudaGetSymbolAddress((void**)&wv2,  g_wv2);
    cudaGetSymbolAddress((void**)&wo2,  g_wo2);
    cudaGetSymbolAddress((void**)&Q2,   g_Q2);
    cudaGetSymbolAddress((void**)&K2,   g_K2);
    cudaGetSymbolAddress((void**)&Vt2,  g_Vt2);

    // 1. split/convert inputs + weights
    split_rows_kernel<<<(M_ROWS * 512 + 255) / 256, 256>>>(x, x2, M_ROWS);
    dim3 wtGrid(32, 32), wtBlock(32, 8);
    split_wT_kernel<<<wtGrid, wtBlock>>>(Wq, wq2);
    split_wT_kernel<<<wtGrid, wtBlock>>>(Wk, wk2);
    split_wT_kernel<<<wtGrid, wtBlock>>>(Wv, wv2);
    split_wT_kernel<<<wtGrid, wtBlock>>>(Wo, wo2);

    // 2. fused Q/K/V projections
    dim3 qkvGrid(D_MODEL / 128, M_ROWS / 128, 3);
    gemm_bf16_kernel<<<qkvGrid, 256>>>(x2, wq2, wk2, wv2, q, k, v, D_MODEL);

    // 3. attention operand prep
    qk2_split_kernel<<<(M_ROWS * 512 + 255) / 256, 256>>>(q, k, Q2, K2);
    vt2_split_kernel<<<dim3(SEQ / 64, 32), 256>>>(v, Vt2);

    // 4. software-pipelined tensor-core flash attention
    cudaFuncSetAttribute(attn_tc_kernel, cudaFuncAttributeMaxDynamicSharedMemorySize,
                         ATT_SMEM);
    attn_tc_kernel<<<dim3(SEQ / 128, 32), 256, ATT_SMEM>>>(Q2, K2, Vt2, ctx2);

    // 5. output projection
    dim3 gemmGrid(D_MODEL / 128, M_ROWS / 128, 1);
    gemm_bf16_kernel<<<gemmGrid, 256>>>(ctx2, wo2, wo2, wo2, out, out, out, D_MODEL);
}

// round 16
// speedup vs baseline: 1.1037x; 1.1037x over previous
#include <cuda_runtime.h>
#include <cuda_bf16.h>
#include <cuda_fp16.h>
#include <stdint.h>
#include <math.h>

#define D_MODEL 1024
#define N_HEAD 16
#define HEAD_DIM 64
#define BATCH 2
#define SEQ 2048
#define M_ROWS (BATCH * SEQ)   // 4096
#define KP 3072                // split K' for projections (bf16 3-term)
#define AQP 64                 // attention Q width (single fp16)
#define AKP2 128               // attention K width (kh|kl fp16)
#define AVP 128                // attention V width (vh|vl fp16)

// ---------------- scratch ----------------
__device__ float g_q[M_ROWS * D_MODEL];
__device__ float g_k[M_ROWS * D_MODEL];
__device__ float g_v[M_ROWS * D_MODEL];

__device__ __nv_bfloat16 g_x2[M_ROWS * KP];      // [Ah | Ah | Al]
__device__ __nv_bfloat16 g_ctx2[M_ROWS * KP];    // written by attention epilogue
__device__ __nv_bfloat16 g_wq2[D_MODEL * KP];    // [Wh^T | Wl^T | Wh^T]
__device__ __nv_bfloat16 g_wk2[D_MODEL * KP];
__device__ __nv_bfloat16 g_wv2[D_MODEL * KP];
__device__ __nv_bfloat16 g_wo2[D_MODEL * KP];

__device__ __half g_Q2[32 * SEQ * AQP];           // [bh][s][qh] (scale*log2e folded)
__device__ __half g_K2[32 * SEQ * AKP2];          // [bh][s][kh|kl]
__device__ __half g_Vt2[32 * HEAD_DIM * 2 * SEQ]; // [bh][dh][t: vh(64)|vl(64)]

// ============================================================================
// helpers
// ============================================================================
__device__ __forceinline__ void split_bf16(float x, __nv_bfloat16& h, __nv_bfloat16& l)
{
    h = __float2bfloat16(x);
    l = __float2bfloat16(x - __bfloat162float(h));
}

__device__ __forceinline__ void split_f16(float x, __half& h, __half& l)
{
    h = __float2half(x);
    l = __float2half(x - __half2float(h));
}

__device__ __forceinline__ float ex2f(float x)
{
    float y;
    asm("ex2.approx.ftz.f32 %0, %1;" : "=f"(y) : "f"(x));
    return y;
}

__device__ __forceinline__ void mma16816bf(float c[4],
    uint32_t a0, uint32_t a1, uint32_t a2, uint32_t a3, uint32_t b0, uint32_t b1)
{
    asm volatile(
        "mma.sync.aligned.m16n8k16.row.col.f32.bf16.bf16.f32 "
        "{%0,%1,%2,%3}, {%4,%5,%6,%7}, {%8,%9}, {%0,%1,%2,%3};\n"
        : "+f"(c[0]), "+f"(c[1]), "+f"(c[2]), "+f"(c[3])
        : "r"(a0), "r"(a1), "r"(a2), "r"(a3), "r"(b0), "r"(b1));
}

__device__ __forceinline__ void mma16816h(float c[4],
    uint32_t a0, uint32_t a1, uint32_t a2, uint32_t a3, uint32_t b0, uint32_t b1)
{
    asm volatile(
        "mma.sync.aligned.m16n8k16.row.col.f32.f16.f16.f32 "
        "{%0,%1,%2,%3}, {%4,%5,%6,%7}, {%8,%9}, {%0,%1,%2,%3};\n"
        : "+f"(c[0]), "+f"(c[1]), "+f"(c[2]), "+f"(c[3])
        : "r"(a0), "r"(a1), "r"(a2), "r"(a3), "r"(b0), "r"(b1));
}

__device__ __forceinline__ void ldsm4(uint32_t& r0, uint32_t& r1, uint32_t& r2, uint32_t& r3,
                                      const void* p)
{
    uint32_t a = (uint32_t)__cvta_generic_to_shared(p);
    asm volatile("ldmatrix.sync.aligned.m8n8.x4.shared.b16 {%0,%1,%2,%3}, [%4];\n"
                 : "=r"(r0), "=r"(r1), "=r"(r2), "=r"(r3) : "r"(a));
}

__device__ __forceinline__ void cpa16(void* sdst, const void* gsrc)
{
    uint32_t sa = (uint32_t)__cvta_generic_to_shared(sdst);
    asm volatile("cp.async.cg.shared.global [%0], [%1], 16;\n" :: "r"(sa), "l"(gsrc));
}
__device__ __forceinline__ void cpa_commit() { asm volatile("cp.async.commit_group;\n"); }
template <int N>
__device__ __forceinline__ void cpa_wait() { asm volatile("cp.async.wait_group %0;\n" :: "n"(N)); }

// ============================================================================
// Split input rows: X[M][1024] fp32 -> X2[M][3072] bf16 = [h | h | l]
// ============================================================================
__global__ void split_rows_kernel(const float* __restrict__ X,
                                  __nv_bfloat16* __restrict__ X2, int M)
{
    int idx = blockIdx.x * blockDim.x + threadIdx.x;
    if (idx >= M * 512) return;
    int r = idx >> 9;
    int c = (idx & 511) * 2;
    float2 v = *(const float2*)&X[(size_t)r * D_MODEL + c];
    __nv_bfloat16 h0, l0, h1, l1;
    split_bf16(v.x, h0, l0);
    split_bf16(v.y, h1, l1);
    __nv_bfloat162 hh; hh.x = h0; hh.y = h1;
    __nv_bfloat162 ll; ll.x = l0; ll.y = l1;
    size_t base = (size_t)r * KP + c;
    *(__nv_bfloat162*)&X2[base]             = hh;
    *(__nv_bfloat162*)&X2[base + D_MODEL]   = hh;
    *(__nv_bfloat162*)&X2[base + 2*D_MODEL] = ll;
}

// Split + transpose weights: W[K][N] fp32 -> B2t[N][3072] = [h | l | h]
__global__ void split_wT_kernel(const float* __restrict__ W,
                                __nv_bfloat16* __restrict__ B2t)
{
    __shared__ float t[32][33];
    const int k0 = blockIdx.y * 32, n0 = blockIdx.x * 32;
    const int tx = threadIdx.x, ty = threadIdx.y;
#pragma unroll
    for (int i = 0; i < 4; i++)
        t[ty + i * 8][tx] = W[(size_t)(k0 + ty + i * 8) * D_MODEL + n0 + tx];
    __syncthreads();
#pragma unroll
    for (int i = 0; i < 4; i++) {
        int n = n0 + ty + i * 8;
        int k = k0 + tx;
        float v = t[tx][ty + i * 8];
        __nv_bfloat16 h, l;
        split_bf16(v, h, l);
        size_t base = (size_t)n * KP;
        B2t[base + k]              = h;
        B2t[base + D_MODEL + k]    = l;
        B2t[base + 2*D_MODEL + k]  = h;
    }
}

// ============================================================================
// Q/K attention prep (fp16). Q: single fp16, scale*log2(e) folded.
// K: [kh | kl] exact fp16 split.
// ============================================================================
__global__ void qk2_split_kernel(const float* __restrict__ Qf,
                                 const float* __restrict__ Kf,
                                 __half* __restrict__ Q2,
                                 __half* __restrict__ K2)
{
    const float QSCALE = 0.125f * 1.44269504088896f;
    int idx = blockIdx.x * blockDim.x + threadIdx.x;
    if (idx >= M_ROWS * 512) return;
    int r  = idx >> 9;
    int c2 = (idx & 511) * 2;
    int h  = c2 >> 6;
    int d  = c2 & 63;
    int b  = r / SEQ, s = r % SEQ;
    int bh = b * N_HEAD + h;

    float2 qv = *(const float2*)&Qf[(size_t)r * D_MODEL + c2];
    __half2 qh = __floats2half2_rn(qv.x * QSCALE, qv.y * QSCALE);
    *(__half2*)&Q2[((size_t)bh * SEQ + s) * AQP + d] = qh;

    float2 kv = *(const float2*)&Kf[(size_t)r * D_MODEL + c2];
    __half kh0, kl0, kh1, kl1;
    split_f16(kv.x, kh0, kl0);
    split_f16(kv.y, kh1, kl1);
    __half2 kh; kh.x = kh0; kh.y = kh1;
    __half2 kl; kl.x = kl0; kl.y = kl1;
    size_t kbase = ((size_t)bh * SEQ + s) * AKP2;
    *(__half2*)&K2[kbase + d]      = kh;
    *(__half2*)&K2[kbase + 64 + d] = kl;
}

// ============================================================================
// V transpose+split (fp16): fp32 -> Vt2[bh][dh][t*128 + {vh(64)|vl(64)}]
// ============================================================================
__global__ void vt2_split_kernel(const float* __restrict__ Vf,
                                 __half* __restrict__ Vt2)
{
    __shared__ float tile[64][65];
    const int t  = blockIdx.x;
    const int bh = blockIdx.y;
    const int b  = bh >> 4, h = bh & 15;
    const int tid = threadIdx.x;

#pragma unroll
    for (int i = 0; i < 16; i++) {
        int e = i * 256 + tid;
        int s = e >> 6, d = e & 63;
        tile[s][d] = Vf[((size_t)(b * SEQ + t * 64 + s)) * D_MODEL + h * 64 + d];
    }
    __syncthreads();
#pragma unroll
    for (int i = 0; i < 16; i++) {
        int e  = i * 256 + tid;
        int dh = e >> 6, kv = e & 63;
        float v = tile[kv][dh];
        __half vh, vl;
        split_f16(v, vh, vl);
        size_t base = ((size_t)bh * 64 + dh) * (2 * SEQ) + (size_t)t * AVP;
        Vt2[base + kv]       = vh;
        Vt2[base + 64 + kv]  = vl;
    }
}

// ============================================================================
// bf16 tensor-core GEMM (projections; unchanged, proven).
// ============================================================================
#define TBK 32
#define TLD 40

__global__ __launch_bounds__(256)
void gemm_bf16_kernel(const __nv_bfloat16* __restrict__ A,
                      const __nv_bfloat16* __restrict__ Bt0,
                      const __nv_bfloat16* __restrict__ Bt1,
                      const __nv_bfloat16* __restrict__ Bt2,
                      float* __restrict__ C0,
                      float* __restrict__ C1,
                      float* __restrict__ C2,
                      int N)
{
    const __nv_bfloat16* Bt = (blockIdx.z == 0) ? Bt0 : (blockIdx.z == 1) ? Bt1 : Bt2;
    float* C = (blockIdx.z == 0) ? C0 : (blockIdx.z == 1) ? C1 : C2;

    __shared__ __nv_bfloat16 As[128 * TLD];
    __shared__ __nv_bfloat16 Bs[128 * TLD];

    const int tid  = threadIdx.x;
    const int wid  = tid >> 5;
    const int lane = tid & 31;
    const int g    = lane >> 2;
    const int q4   = lane & 3;
    const int warp_m = wid >> 2;
    const int warp_n = wid & 3;
    const int rowBase = blockIdx.y * 128;
    const int colBase = blockIdx.x * 128;

    float acc[4][4][4];
#pragma unroll
    for (int im = 0; im < 4; im++)
#pragma unroll
        for (int in = 0; in < 4; in++)
#pragma unroll
            for (int e = 0; e < 4; e++) acc[im][in][e] = 0.f;

    uint4 pa[2], pb[2];
    const int lr0 = tid >> 2;
    const int lc  = (tid & 3) * 8;

    auto loadTile = [&](int k0) {
        pa[0] = *(const uint4*)&A [(size_t)(rowBase + lr0)      * KP + k0 + lc];
        pa[1] = *(const uint4*)&A [(size_t)(rowBase + lr0 + 64) * KP + k0 + lc];
        pb[0] = *(const uint4*)&Bt[(size_t)(colBase + lr0)      * KP + k0 + lc];
        pb[1] = *(const uint4*)&Bt[(size_t)(colBase + lr0 + 64) * KP + k0 + lc];
    };
    auto storeTile = [&]() {
        *(uint4*)&As[(lr0)      * TLD + lc] = pa[0];
        *(uint4*)&As[(lr0 + 64) * TLD + lc] = pa[1];
        *(uint4*)&Bs[(lr0)      * TLD + lc] = pb[0];
        *(uint4*)&Bs[(lr0 + 64) * TLD + lc] = pb[1];
    };

    loadTile(0);
    storeTile();
    __syncthreads();

    for (int k0 = 0; k0 < KP; k0 += TBK) {
        bool more = (k0 + TBK) < KP;
        if (more) loadTile(k0 + TBK);

#pragma unroll
        for (int ks = 0; ks < 2; ks++) {
            const int kk = ks * 16 + q4 * 2;
            uint32_t bfr[4][2];
#pragma unroll
            for (int in = 0; in < 4; in++) {
                int n = warp_n * 32 + in * 8 + g;
                bfr[in][0] = *(const uint32_t*)&Bs[n * TLD + kk];
                bfr[in][1] = *(const uint32_t*)&Bs[n * TLD + kk + 8];
            }
#pragma unroll
            for (int im = 0; im < 4; im++) {
                int r = warp_m * 64 + im * 16 + g;
                uint32_t a0 = *(const uint32_t*)&As[(r)     * TLD + kk];
                uint32_t a1 = *(const uint32_t*)&As[(r + 8) * TLD + kk];
                uint32_t a2 = *(const uint32_t*)&As[(r)     * TLD + kk + 8];
                uint32_t a3 = *(const uint32_t*)&As[(r + 8) * TLD + kk + 8];
#pragma unroll
                for (int in = 0; in < 4; in++)
                    mma16816bf(acc[im][in], a0, a1, a2, a3, bfr[in][0], bfr[in][1]);
            }
        }
        __syncthreads();
        if (more) {
            storeTile();
            __syncthreads();
        }
    }

#pragma unroll
    for (int im = 0; im < 4; im++) {
        int r0 = rowBase + warp_m * 64 + im * 16 + g;
#pragma unroll
        for (int in = 0; in < 4; in++) {
            int col = colBase + warp_n * 32 + in * 8 + q4 * 2;
            float2 v0 = make_float2(acc[im][in][0], acc[im][in][1]);
            float2 v1 = make_float2(acc[im][in][2], acc[im][in][3]);
            *(float2*)&C[(size_t)(r0)     * N + col] = v0;
            *(float2*)&C[(size_t)(r0 + 8) * N + col] = v1;
        }
    }
}

// ============================================================================
// Tensor-core causal flash attention — fp16 operands, reduced mma count.
// QK: q(fp16) x [kh|kl] = 8 ksteps.  PV: p(fp16) x [vh|vl] = 8 ksteps.
// 2 smem buffers (34KB each), 2 CTAs/SM target, 1 sync/tile.
// CTA = (b,h) x 128 q rows; 8 warps x 16 q rows; BKV = 64.
// ============================================================================
#define KLD 136                          // K tile leading dim (fp16 elems)
#define VLD 136                          // V tile leading dim
#define KT_E (64 * KLD)                  // 8704 elems
#define VT_E (64 * VLD)                  // 8704 elems
#define BUF_E (KT_E + VT_E)              // 17408 elems
#define NSTG 2
#define ATT_SMEM (NSTG * BUF_E * 2)      // 69632 bytes

extern __shared__ __half attn_sm[];

__global__ __launch_bounds__(256, 2)
void attn_tc_kernel(const __half* __restrict__ Q2,
                    const __half* __restrict__ K2,
                    const __half* __restrict__ Vt2,
                    __nv_bfloat16* __restrict__ ctx2)
{
    const int tid  = threadIdx.x;
    const int w    = tid >> 5;
    const int lane = tid & 31;
    const int g    = lane >> 2;
    const int q4   = lane & 3;
    const int bh   = blockIdx.y;
    const int b    = bh >> 4, h = bh & 15;
    const int q0   = (gridDim.x - 1 - blockIdx.x) * 128;   // heavy CTAs first
    const int nt   = q0 / 64 + 2;
    const int qw   = q0 + w * 16;

    // per-lane LDSM base offsets
    const int rowN  = lane & 7;
    const int ksel  = (lane >> 3) & 1;
    const int jsel  = lane >> 4;
    const int kOffE = (jsel * 8 + rowN) * KLD + ksel * 8;
    const int vOffE = (jsel * 8 + rowN) * VLD + ksel * 8;

    // ---- Q fragments: 4 ksteps only (single fp16 q, reused across K phases)
    uint32_t qa[4][4];
    {
        const __half* Qbase = Q2 + ((size_t)bh * SEQ + qw) * AQP;
#pragma unroll
        for (int f = 0; f < 4; f++) {
            int kk = f * 16 + 2 * q4;
            qa[f][0] = *(const uint32_t*)&Qbase[(g)     * AQP + kk];
            qa[f][1] = *(const uint32_t*)&Qbase[(g + 8) * AQP + kk];
            qa[f][2] = *(const uint32_t*)&Qbase[(g)     * AQP + kk + 8];
            qa[f][3] = *(const uint32_t*)&Qbase[(g + 8) * AQP + kk + 8];
        }
    }

    const __half* Kg = K2  + (size_t)bh * SEQ * AKP2;
    const __half* Vg = Vt2 + (size_t)bh * HEAD_DIM * (2 * SEQ);

    auto issueTile = [&](int t) {
        const __half* ksrc = Kg + (size_t)t * 64 * AKP2;
        const __half* vsrc = Vg + (size_t)t * AVP;
        __half* kd = attn_sm + (t & 1) * BUF_E;
        __half* vd = kd + KT_E;
#pragma unroll
        for (int i = 0; i < 4; i++) {            // K: 64 rows x 16 chunks
            int c   = i * 256 + tid;
            int row = c >> 4;
            int col = (c & 15) * 8;
            cpa16(&kd[row * KLD + col], &ksrc[row * AKP2 + col]);
        }
#pragma unroll
        for (int i = 0; i < 4; i++) {            // V: 64 rows x 16 chunks
            int c   = i * 256 + tid;
            int row = c >> 4;
            int col = (c & 15) * 8;
            cpa16(&vd[row * VLD + col], &vsrc[(size_t)row * (2 * SEQ) + col]);
        }
        cpa_commit();
    };

    float O[8][4];
#pragma unroll
    for (int j = 0; j < 8; j++)
#pragma unroll
        for (int e = 0; e < 4; e++) O[j][e] = 0.f;
    float m0 = -INFINITY, m1 = -INFINITY, l0 = 0.f, l1 = 0.f;

    issueTile(0);

    for (int t = 0; t < nt; t++) {
        cpa_wait<0>();     // tile t complete (only group in flight)
        __syncthreads();   // visible to all; buffer (t+1)&1 free (read in iter t-1)

        if (t + 1 < nt) issueTile(t + 1);   // overlaps compute

        const int k0 = t * 64;
        if (k0 <= qw + 15) {                 // skip fully-masked warp tiles
            const __half* Ks = attn_sm + (t & 1) * BUF_E;
            const __half* Vs = Ks + KT_E;

            // ---- QK^T: 8 ksteps (kh phase 0-3, kl phase 4-7), q reused ----
            float S_[8][4];
#pragma unroll
            for (int j = 0; j < 8; j++)
#pragma unroll
                for (int e = 0; e < 4; e++) S_[j][e] = 0.f;

#pragma unroll
            for (int s = 0; s < 8; s++) {
                const int f = s & 3;
                uint32_t a0 = qa[f][0], a1 = qa[f][1], a2 = qa[f][2], a3 = qa[f][3];
#pragma unroll
                for (int jj = 0; jj < 4; jj++) {
                    uint32_t b0, b1, b2, b3;
                    ldsm4(b0, b1, b2, b3, Ks + kOffE + jj * 16 * KLD + s * 16);
                    mma16816h(S_[2 * jj],     a0, a1, a2, a3, b0, b1);
                    mma16816h(S_[2 * jj + 1], a0, a1, a2, a3, b2, b3);
                }
            }

            // ---- causal mask ----
            if (k0 + 63 > qw) {
                const int r0 = qw + g, r1 = r0 + 8;
#pragma unroll
                for (int j = 0; j < 8; j++) {
                    int c0 = k0 + j * 8 + 2 * q4;
                    if (c0     > r0) S_[j][0] = -INFINITY;
                    if (c0 + 1 > r0) S_[j][1] = -INFINITY;
                    if (c0     > r1) S_[j][2] = -INFINITY;
                    if (c0 + 1 > r1) S_[j][3] = -INFINITY;
                }
            }

            // ---- online softmax (exp2 domain); P packed as single fp16 ----
            float rmax0 = -INFINITY, rmax1 = -INFINITY;
#pragma unroll
            for (int j = 0; j < 8; j++) {
                rmax0 = fmaxf(rmax0, fmaxf(S_[j][0], S_[j][1]));
                rmax1 = fmaxf(rmax1, fmaxf(S_[j][2], S_[j][3]));
            }
            rmax0 = fmaxf(rmax0, __shfl_xor_sync(0xffffffffu, rmax0, 1));
            rmax0 = fmaxf(rmax0, __shfl_xor_sync(0xffffffffu, rmax0, 2));
            rmax1 = fmaxf(rmax1, __shfl_xor_sync(0xffffffffu, rmax1, 1));
            rmax1 = fmaxf(rmax1, __shfl_xor_sync(0xffffffffu, rmax1, 2));

            float nm0 = fmaxf(m0, rmax0), nm1 = fmaxf(m1, rmax1);
            float corr0 = ex2f(m0 - nm0), corr1 = ex2f(m1 - nm1);
            m0 = nm0; m1 = nm1;

            uint32_t ph[8][2];
            float sum0 = 0.f, sum1 = 0.f;
#pragma unroll
            for (int j = 0; j < 8; j++) {
                float p00 = ex2f(S_[j][0] - nm0);
                float p01 = ex2f(S_[j][1] - nm0);
                float p10 = ex2f(S_[j][2] - nm1);
                float p11 = ex2f(S_[j][3] - nm1);
                sum0 += p00 + p01;
                sum1 += p10 + p11;
                __half2 h0 = __floats2half2_rn(p00, p01);
                __half2 h1 = __floats2half2_rn(p10, p11);
                ph[j][0] = *(uint32_t*)&h0;
                ph[j][1] = *(uint32_t*)&h1;
            }
            sum0 += __shfl_xor_sync(0xffffffffu, sum0, 1);
            sum0 += __shfl_xor_sync(0xffffffffu, sum0, 2);
            sum1 += __shfl_xor_sync(0xffffffffu, sum1, 1);
            sum1 += __shfl_xor_sync(0xffffffffu, sum1, 2);
            l0 = l0 * corr0 + sum0;
            l1 = l1 * corr1 + sum1;

#pragma unroll
            for (int j = 0; j < 8; j++) {
                O[j][0] *= corr0; O[j][1] *= corr0;
                O[j][2] *= corr1; O[j][3] *= corr1;
            }

            // ---- PV: 8 ksteps (vh phase 0-3, vl phase 4-7), all with ph ----
#pragma unroll
            for (int s = 0; s < 8; s++) {
                const int ksp = s & 3;
                uint32_t h0 = ph[2 * ksp][0],     h1 = ph[2 * ksp][1];
                uint32_t h2 = ph[2 * ksp + 1][0], h3 = ph[2 * ksp + 1][1];
#pragma unroll
                for (int jj = 0; jj < 4; jj++) {
                    uint32_t b0, b1, b2, b3;
                    ldsm4(b0, b1, b2, b3, Vs + vOffE + jj * 16 * VLD + s * 16);
                    mma16816h(O[2 * jj],     h0, h1, h2, h3, b0, b1);
                    mma16816h(O[2 * jj + 1], h0, h1, h2, h3, b2, b3);
                }
            }
        }
    }

    // ---- epilogue: write [h|h|l] bf16 split of ctx directly ----
    const float inv0 = 1.f / l0, inv1 = 1.f / l1;
    const int r0 = b * SEQ + qw + g;
    const int colBase = h * HEAD_DIM + 2 * q4;
#pragma unroll
    for (int jn = 0; jn < 8; jn++) {
        int col = colBase + jn * 8;
        float v00 = O[jn][0] * inv0, v01 = O[jn][1] * inv0;
        float v10 = O[jn][2] * inv1, v11 = O[jn][3] * inv1;
        __nv_bfloat16 h00, l00, h01, l01, h10, l10, h11, l11;
        split_bf16(v00, h00, l00); split_bf16(v01, h01, l01);
        split_bf16(v10, h10, l10); split_bf16(v11, h11, l11);
        __nv_bfloat162 hh0; hh0.x = h00; hh0.y = h01;
        __nv_bfloat162 ll0; ll0.x = l00; ll0.y = l01;
        __nv_bfloat162 hh1; hh1.x = h10; hh1.y = h11;
        __nv_bfloat162 ll1; ll1.x = l10; ll1.y = l11;
        size_t base0 = (size_t)r0 * KP + col;
        size_t base1 = base0 + (size_t)8 * KP;
        *(uint32_t*)&ctx2[base0]             = *(uint32_t*)&hh0;
        *(uint32_t*)&ctx2[base0 + D_MODEL]   = *(uint32_t*)&hh0;
        *(uint32_t*)&ctx2[base0 + 2*D_MODEL] = *(uint32_t*)&ll0;
        *(uint32_t*)&ctx2[base1]             = *(uint32_t*)&hh1;
        *(uint32_t*)&ctx2[base1 + D_MODEL]   = *(uint32_t*)&hh1;
        *(uint32_t*)&ctx2[base1 + 2*D_MODEL] = *(uint32_t*)&ll1;
    }
}

// ============================================================================
// Launch
// ============================================================================
extern "C" void kernel_launch(void* const* d_in, const int* in_sizes, int n_in,
                              void* d_out, int out_size)
{
    const float* x  = (const float*)d_in[0];
    const float* Wq = (const float*)d_in[1];
    const float* Wk = (const float*)d_in[2];
    const float* Wv = (const float*)d_in[3];
    const float* Wo = (const float*)d_in[4];
    float* out = (float*)d_out;

    float *q, *k, *v;
    __nv_bfloat16 *x2, *ctx2, *wq2, *wk2, *wv2, *wo2;
    __half *Q2, *K2, *Vt2;
    cudaGetSymbolAddress((void**)&q,    g_q);
    cudaGetSymbolAddress((void**)&k,    g_k);
    cudaGetSymbolAddress((void**)&v,    g_v);
    cudaGetSymbolAddress((void**)&x2,   g_x2);
    cudaGetSymbolAddress((void**)&ctx2, g_ctx2);
    cudaGetSymbolAddress((void**)&wq2,  g_wq2);
    cudaGetSymbolAddress((void**)&wk2,  g_wk2);
    cudaGetSymbolAddress((void**)&wv2,  g_wv2);
    cudaGetSymbolAddress((void**)&wo2,  g_wo2);
    cudaGetSymbolAddress((void**)&Q2,   g_Q2);
    cudaGetSymbolAddress((void**)&K2,   g_K2);
    cudaGetSymbolAddress((void**)&Vt2,  g_Vt2);

    // 1. split/convert inputs + weights
    split_rows_kernel<<<(M_ROWS * 512 + 255) / 256, 256>>>(x, x2, M_ROWS);
    dim3 wtGrid(32, 32), wtBlock(32, 8);
    split_wT_kernel<<<wtGrid, wtBlock>>>(Wq, wq2);
    split_wT_kernel<<<wtGrid, wtBlock>>>(Wk, wk2);
    split_wT_kernel<<<wtGrid, wtBlock>>>(Wv, wv2);
    split_wT_kernel<<<wtGrid, wtBlock>>>(Wo, wo2);

    // 2. fused Q/K/V projections
    dim3 qkvGrid(D_MODEL / 128, M_ROWS / 128, 3);
    gemm_bf16_kernel<<<qkvGrid, 256>>>(x2, wq2, wk2, wv2, q, k, v, D_MODEL);

    // 3. attention operand prep (fp16)
    qk2_split_kernel<<<(M_ROWS * 512 + 255) / 256, 256>>>(q, k, Q2, K2);
    vt2_split_kernel<<<dim3(SEQ / 64, 32), 256>>>(v, Vt2);

    // 4. fp16 tensor-core flash attention (2 buffers, 2 CTAs/SM)
    cudaFuncSetAttribute(attn_tc_kernel, cudaFuncAttributeMaxDynamicSharedMemorySize,
                         ATT_SMEM);
    attn_tc_kernel<<<dim3(SEQ / 128, 32), 256, ATT_SMEM>>>(Q2, K2, Vt2, ctx2);

    // 5. output projection
    dim3 gemmGrid(D_MODEL / 128, M_ROWS / 128, 1);
    gemm_bf16_kernel<<<gemmGrid, 256>>>(ctx2, wo2, wo2, wo2, out, out, out, D_MODEL);
}